// round 5
// baseline (speedup 1.0000x reference)
#include <cuda_runtime.h>

#define W_IMG  1248
#define NROWS  768
#define SEG    320            // outputs per warp-segment (4 segs/row, 4*320=1280)
#define HALO   192
#define NT     128            // 4 warps = 4 segments = 1 row per CTA
#define C      16             // elements per thread; 192 = 12*16 exactly

__global__ __launch_bounds__(NT) void stereo_warp_kernel(
    const float* __restrict__ L,
    const float* __restrict__ R,
    float* __restrict__ out)
{
    const int row  = blockIdx.x;
    const int tid  = threadIdx.x;
    const int lane = tid & 31;
    const int seg  = tid >> 5;                 // 0..3

    const float* __restrict__ r = R + (size_t)row * W_IMG;
    const float* __restrict__ l = L + (size_t)row * W_IMG;
    float* __restrict__ o = out + (size_t)row * W_IMG;

    const int u0 = lane * C;                   // local coord base (0..496)
    const int j0 = seg * SEG - HALO + u0;      // global column of this chunk
    // whole-chunk predicates (all boundaries multiples of 16)
    const bool inr  = (j0 >= 0) && (j0 + C <= W_IMG);        // r-load validity
    const bool outv = (u0 >= HALO) && (j0 + C <= W_IMG);     // output validity

    // ---- all global loads issued up front (8 x LDG.128, MLP=8) ----
    float rv[C];
    float lv[C];
    if (inr) {
        #pragma unroll
        for (int v = 0; v < 4; v++)
            *(float4*)(rv + 4 * v) = *(const float4*)(r + j0 + 4 * v);
    } else {
        #pragma unroll
        for (int s = 0; s < C; s++) rv[s] = 0.f;
    }
    if (outv) {
        #pragma unroll
        for (int v = 0; v < 4; v++)
            *(float4*)(lv + 4 * v) = *(const float4*)(l + j0 + 4 * v);
    }

    // ---- serial scan of 16-chunk in local coords ----
    float lp[C], lq[C];
    float p = 0.f, q = 0.f;
    #pragma unroll
    for (int s = 0; s < C; s++) {
        p += rv[s];
        q = fmaf((float)(u0 + s), rv[s], q);
        lp[s] = p;
        lq[s] = q;
    }

    // ---- inclusive warp scan of (p, q) thread totals ----
    float vp = p, vq = q;
    #pragma unroll
    for (int off = 1; off < 32; off <<= 1) {
        float ap = __shfl_up_sync(0xffffffffu, vp, off);
        float aq = __shfl_up_sync(0xffffffffu, vq, off);
        if (lane >= off) { vp += ap; vq += aq; }
    }
    const float offp = vp - p;
    const float offq = vq - q;
    #pragma unroll
    for (int s = 0; s < C; s++) { lp[s] += offp; lq[s] += offq; }

    // ---- outputs: prefix at u-192 = same position s, lane-12 ----
    float res[C];
    #pragma unroll
    for (int s = 0; s < C; s++) {
        float bp = __shfl_up_sync(0xffffffffu, lp[s], 12);
        float bq = __shfl_up_sync(0xffffffffu, lq[s], 12);
        float S  = (float)(u0 + s) * (lp[s] - bp) - (lq[s] - bq);
        res[s] = lv[s] * S;
    }

    if (outv) {
        #pragma unroll
        for (int v = 0; v < 4; v++)
            *(float4*)(o + j0 + 4 * v) = *(const float4*)(res + 4 * v);
    }
}

extern "C" void kernel_launch(void* const* d_in, const int* in_sizes, int n_in,
                              void* d_out, int out_size)
{
    const float* left  = (const float*)d_in[0];
    const float* right = (const float*)d_in[1];
    float* out = (float*)d_out;
    stereo_warp_kernel<<<NROWS, NT>>>(left, right, out);
}